// round 12
// baseline (speedup 1.0000x reference)
#include <cuda_runtime.h>

#define NC    21
#define HW    (512 * 512)
#define NB    16
#define BHW   (NB * HW)
#define NBINS (NC * NC)

// Confusion-matrix scratch. Zero at module load (BSS); loss_kernel re-zeroes it
// after consuming it, so every launch (incl. graph replays) starts clean.
__device__ unsigned int g_conf[NBINS];

// ---- hist_kernel: frozen fastest-measured configuration (R3/R11) ----
__global__ void __launch_bounds__(256)
hist_kernel(const float* __restrict__ logits, const int* __restrict__ target) {
    __shared__ unsigned int s_conf[NBINS];
    for (int i = threadIdx.x; i < NBINS; i += 256) s_conf[i] = 0u;
    __syncthreads();

    const int nquads = BHW / 4;  // 1,048,576 quads of 4 pixels
    for (int q = blockIdx.x * 256 + threadIdx.x; q < nquads;
         q += gridDim.x * 256) {
        int p = q << 2;                 // pixel index (multiple of 4, stays in same b)
        int b = p / HW;
        int s = p - b * HW;
        const float4* base =
            (const float4*)(logits + (size_t)b * NC * HW + s);

        float4 v = __ldg(base);
        float m0 = v.x, m1 = v.y, m2 = v.z, m3 = v.w;
        int a0 = 0, a1 = 0, a2 = 0, a3 = 0;
        #pragma unroll
        for (int c = 1; c < NC; c++) {
            float4 u = __ldg(base + (size_t)c * (HW / 4));
            if (u.x > m0) { m0 = u.x; a0 = c; }
            if (u.y > m1) { m1 = u.y; a1 = c; }
            if (u.z > m2) { m2 = u.z; a2 = c; }
            if (u.w > m3) { m3 = u.w; a3 = c; }
        }

        int4 t = *(const int4*)(target + p);   // 16B-aligned: p % 4 == 0
        atomicAdd(&s_conf[t.x * NC + a0], 1u);
        atomicAdd(&s_conf[t.y * NC + a1], 1u);
        atomicAdd(&s_conf[t.z * NC + a2], 1u);
        atomicAdd(&s_conf[t.w * NC + a3], 1u);
    }

    __syncthreads();
    for (int i = threadIdx.x; i < NBINS; i += 256) {
        unsigned int v = s_conf[i];
        if (v) atomicAdd(&g_conf[i], v);
    }
}

// ---- loss_kernel: PDL secondary. Prologue overlaps hist tail; the grid
// dependency sync orders all of hist's g_conf flushes before the reads. ----
__global__ void __launch_bounds__(512)
loss_kernel(float* __restrict__ out) {
    __shared__ unsigned int s_conf[NBINS];
    int i = threadIdx.x;

    cudaGridDependencySynchronize();   // wait for hist_kernel full completion

    // Snapshot the confusion matrix, then reset it for the next launch/replay.
    if (i < NBINS) s_conf[i] = g_conf[i];
    __syncthreads();
    if (i < NBINS) g_conf[i] = 0u;

    float acc = 0.0f;
    if (i < NC) {
        float tp = (float)s_conf[i * NC + i];
        float rowsum = 0.0f, colsum = 0.0f;
        #pragma unroll
        for (int j = 0; j < NC; j++) {
            rowsum += (float)s_conf[i * NC + j];
            colsum += (float)s_conf[j * NC + i];
        }
        float fp = rowsum - tp;
        float fn = colsum - tp;
        float tn = (float)BHW - tp - fp - fn;
        float sens = (tp + 1.0f) / (tp + fn + 1.0f);
        float spec = (tn + 1.0f) / (tn + fp + 1.0f);
        acc = 0.5f * sens + 0.5f * spec;
    }
    if (i < 32) {   // classes 0..20 all live in warp 0
        #pragma unroll
        for (int off = 16; off > 0; off >>= 1)
            acc += __shfl_down_sync(0xffffffffu, acc, off);
        if (i == 0) out[0] = 1.0f - acc / (float)NC;
    }
}

extern "C" void kernel_launch(void* const* d_in, const int* in_sizes, int n_in,
                              void* d_out, int out_size) {
    const float* logits = (const float*)d_in[0];
    const int* target   = (const int*)d_in[1];
    float* out = (float*)d_out;

    hist_kernel<<<2048, 256>>>(logits, target);

    // Launch loss_kernel with Programmatic Stream Serialization so its
    // launch/prologue overlaps hist_kernel's tail.
    cudaLaunchAttribute attr;
    attr.id = cudaLaunchAttributeProgrammaticStreamSerialization;
    attr.val.programmaticStreamSerializationAllowed = 1;

    cudaLaunchConfig_t cfg = {};
    cfg.gridDim  = dim3(1, 1, 1);
    cfg.blockDim = dim3(512, 1, 1);
    cfg.dynamicSmemBytes = 0;
    cfg.attrs = &attr;
    cfg.numAttrs = 1;

    cudaLaunchKernelEx(&cfg, loss_kernel, out);
}